// round 2
// baseline (speedup 1.0000x reference)
#include <cuda_runtime.h>

// ---------------- problem constants ----------------
#define BB      256
#define TT      50
#define IDD     16
#define NCV     32
#define D0V     512
#define DINV    528
#define HIDV    512
#define NSTEPS  5
#define DT_C    0.05f

#define HS      1056            // padded row stride of h (1040 used)
#define G_CTAS  136             // 8 row-tiles x 17 col-tiles (worst-case GEMM)
#define NTHR    256

// ---------------- device scratch (no allocations allowed) ----------------
__device__ float g_h[2][BB * HS];        // ping-pong state
__device__ float g_a0[BB * HIDV];        // layer-1 activations
__device__ float g_a1[BB * HIDV];        // layer-2 activations
__device__ int   g_tlast;                // last t with any(mask[:,t] > 0), -1 if none
__device__ unsigned g_bar_cnt;
__device__ volatile unsigned g_bar_gen;

// ---------------- software grid barrier (all 136 CTAs co-resident) ----------
__device__ __forceinline__ void grid_sync() {
    __syncthreads();
    if (threadIdx.x == 0) {
        unsigned gen = g_bar_gen;
        __threadfence();
        if (atomicAdd(&g_bar_cnt, 1u) == G_CTAS - 1u) {
            g_bar_cnt = 0u;
            __threadfence();
            g_bar_gen = gen + 1u;
        } else {
            while (g_bar_gen == gen) { }
        }
        __threadfence();
    }
    __syncthreads();
}

// ---------------- 32x32-tile GEMM phase ----------------
// MODE 0/1: outbuf[row*512 + col] = relu(X@W + bias)        (nw = 512, 16 col tiles)
// MODE 2  : hn[row*HS + 512+col] = hc[row*HS + 512+col] + DT*(X@W + bias)
//           (nw = 528, 17 col tiles, col guard < 528)
template <int MODE>
__device__ __forceinline__ void gemm_phase(const float* __restrict__ X, int xs, int kchunks,
                                           const float* __restrict__ W, int nw,
                                           const float* __restrict__ bias,
                                           float* __restrict__ outbuf,
                                           const float* __restrict__ hc,
                                           float* __restrict__ hn) {
    __shared__ __align__(16) float Xs[16 * 34];   // transposed: Xs[k][row], stride 34
    __shared__ __align__(16) float Ws[16 * 34];   // Ws[k][col], stride 34

    const int ncolt = (MODE == 2) ? 17 : 16;
    const int cta = blockIdx.x;
    const int rt = cta / ncolt;
    const int ct = cta - rt * ncolt;
    const int r0 = rt * 32, c0 = ct * 32;
    const int tid = threadIdx.x;

    // loader indices
    const int lxr = tid >> 4;        // 0..15 (rows lxr, lxr+16)
    const int lxc = tid & 15;        // k within chunk
    const int lwk = tid >> 5;        // 0..7 (k rows lwk, lwk+8)
    const int lwc = tid & 31;        // col within tile

    // compute indices: rows r0+2tr, r0+2tr+1; cols c0+2tc, c0+2tc+1
    const int tr = tid >> 4;         // 0..15
    const int tc = tid & 15;         // 0..15

    float a00 = 0.f, a01 = 0.f, a10 = 0.f, a11 = 0.f;

    const bool wc_ok0 = (c0 + lwc) < nw;   // W col guard (only matters for nw=528 last tile)

    for (int kc = 0; kc < kchunks; kc++) {
        const int k0 = kc * 16;
        __syncthreads();
        // load X chunk (32 rows x 16 k), stored transposed
        {
            float v0 = X[(r0 + lxr) * xs + k0 + lxc];
            float v1 = X[(r0 + lxr + 16) * xs + k0 + lxc];
            Xs[lxc * 34 + lxr] = v0;
            Xs[lxc * 34 + lxr + 16] = v1;
        }
        // load W chunk (16 k x 32 cols)
        {
            float w0 = wc_ok0 ? W[(k0 + lwk) * nw + c0 + lwc] : 0.f;
            float w1 = wc_ok0 ? W[(k0 + lwk + 8) * nw + c0 + lwc] : 0.f;
            Ws[lwk * 34 + lwc] = w0;
            Ws[(lwk + 8) * 34 + lwc] = w1;
        }
        __syncthreads();
        #pragma unroll
        for (int k = 0; k < 16; k++) {
            float2 xp = *(const float2*)&Xs[k * 34 + 2 * tr];
            float2 wp = *(const float2*)&Ws[k * 34 + 2 * tc];
            a00 = fmaf(xp.x, wp.x, a00);
            a01 = fmaf(xp.x, wp.y, a01);
            a10 = fmaf(xp.y, wp.x, a10);
            a11 = fmaf(xp.y, wp.y, a11);
        }
    }
    __syncthreads();   // protect smem before next phase reuses it

    const int ra = r0 + 2 * tr;
    const int ca = c0 + 2 * tc;
    if (MODE != 2) {
        float b0 = bias[ca], b1v = bias[ca + 1];
        float o00 = fmaxf(a00 + b0, 0.f), o01 = fmaxf(a01 + b1v, 0.f);
        float o10 = fmaxf(a10 + b0, 0.f), o11 = fmaxf(a11 + b1v, 0.f);
        *(float2*)&outbuf[ra * 512 + ca] = make_float2(o00, o01);
        *(float2*)&outbuf[(ra + 1) * 512 + ca] = make_float2(o10, o11);
    } else {
        if (ca < DINV) {
            float b0 = bias[ca];
            hn[ra * HS + 512 + ca] = hc[ra * HS + 512 + ca] + DT_C * (a00 + b0);
            hn[(ra + 1) * HS + 512 + ca] = hc[(ra + 1) * HS + 512 + ca] + DT_C * (a10 + b0);
        }
        if (ca + 1 < DINV) {
            float b1v = bias[ca + 1];
            hn[ra * HS + 512 + ca + 1] = hc[ra * HS + 512 + ca + 1] + DT_C * (a01 + b1v);
            hn[(ra + 1) * HS + 512 + ca + 1] = hc[(ra + 1) * HS + 512 + ca + 1] + DT_C * (a11 + b1v);
        }
    }
}

// ---------------- cn0 ODE phase (CTAs 128..135, runs during GEMM-1) ----------
// hn[b, i*32+n] = h[b, i*32+n] + DT*( sum_k cn0[b,i,k]*A[n,k] + Bv[n]*cn1[b,i] )
__device__ __forceinline__ void cnode_phase(const float* __restrict__ A,
                                            const float* __restrict__ Bv,
                                            const float* __restrict__ hc,
                                            float* __restrict__ hn) {
    __shared__ __align__(16) float As[NCV * NCV];
    __shared__ float Bs[NCV];
    const int tid = threadIdx.x;
    const int lcta = blockIdx.x - 128;      // 0..7
    for (int i = tid; i < NCV * NCV; i += NTHR) As[i] = A[i];
    if (tid < NCV) Bs[tid] = Bv[tid];
    __syncthreads();

    const int base = lcta * NTHR + tid;     // 0..2047
    #pragma unroll
    for (int rep = 0; rep < 2; rep++) {
        const int row = base + rep * 2048;  // 0..4095 = b*16 + i
        const int b = row >> 4;
        const int i = row & 15;
        const float* hr = hc + b * HS;
        float x[32];
        const float4* cp = (const float4*)(hr + i * 32);
        #pragma unroll
        for (int q = 0; q < 8; q++) {
            float4 v = cp[q];
            x[4 * q] = v.x; x[4 * q + 1] = v.y; x[4 * q + 2] = v.z; x[4 * q + 3] = v.w;
        }
        const float cn1v = hr[512 + i];
        float* outp = hn + b * HS + i * 32;
        #pragma unroll 4
        for (int n = 0; n < 32; n++) {
            float acc = Bs[n] * cn1v;
            const float4* ap = (const float4*)(As + n * 32);
            #pragma unroll
            for (int q = 0; q < 8; q++) {
                float4 a4 = ap[q];
                acc = fmaf(x[4 * q], a4.x, acc);
                acc = fmaf(x[4 * q + 1], a4.y, acc);
                acc = fmaf(x[4 * q + 2], a4.z, acc);
                acc = fmaf(x[4 * q + 3], a4.w, acc);
            }
            outp[n] = x[n] + DT_C * acc;
        }
    }
}

// ---------------- observation update (all CTAs) ----------------
__device__ __forceinline__ void obs_phase(int t, const float* __restrict__ Y,
                                          const float* __restrict__ mask,
                                          float* __restrict__ h,
                                          float* __restrict__ out,
                                          long off_traj, long off_lasth, int tlast) {
    const int gtid = blockIdx.x * NTHR + threadIdx.x;
    const int nth = G_CTAS * NTHR;
    for (int idx = gtid; idx < BB * DINV; idx += nth) {
        const int b = idx / DINV;
        const int c = idx - b * DINV;
        const float m = mask[b * TT + t];
        float* hr = h + b * HS;
        const float he = hr[512 + c];
        if (c < IDD) {
            const long po = (long)(b * TT + t) * IDD + c;
            out[po] = he;                      // y_preds
            if (off_traj >= 0) out[off_traj + po] = he;   // y_traj
            const float y = Y[(b * TT + t) * IDD + c];
            hr[512 + c] = m * y + (1.f - m) * he;
        } else {
            const int j = c - IDD;             // 0..511
            hr[512 + c] = m * hr[j] + (1.f - m) * he;
        }
    }
    if (t == tlast) {
        for (int idx = gtid; idx < BB * D0V; idx += nth) {
            const int b = idx >> 9;
            const int j = idx & 511;
            out[off_lasth + idx] = h[b * HS + j];
        }
    }
}

// ---------------- persistent kernel ----------------
__global__ void __launch_bounds__(NTHR, 1)
cnode_persistent(const float* __restrict__ Y, const float* __restrict__ mask,
                 const float* __restrict__ A, const float* __restrict__ Bv,
                 const float* __restrict__ W1, const float* __restrict__ b1,
                 const float* __restrict__ W2, const float* __restrict__ b2,
                 const float* __restrict__ W3, const float* __restrict__ b3,
                 float* __restrict__ out,
                 long off_traj, long off_lasth, long off_hfin) {
    int cur = 0;
    const int tlast = g_tlast;
    for (int t = 0; t < TT; t++) {
        for (int s = 0; s < NSTEPS; s++) {
            float* hc = g_h[cur];
            float* hn = g_h[cur ^ 1];
            // phase 1: GEMM1 (128 CTAs) + cn_ode (8 CTAs)
            if (blockIdx.x < 128)
                gemm_phase<0>(hc + 512, HS, 33, W1, HIDV, b1, g_a0, nullptr, nullptr);
            else
                cnode_phase(A, Bv, hc, hn);
            grid_sync();
            // phase 2: GEMM2 (128 CTAs)
            if (blockIdx.x < 128)
                gemm_phase<1>(g_a0, HIDV, 32, W2, HIDV, b2, g_a1, nullptr, nullptr);
            grid_sync();
            // phase 3: GEMM3 + euler update of cn1 part (136 CTAs)
            gemm_phase<2>(g_a1, HIDV, 32, W3, DINV, b3, nullptr, hc, hn);
            grid_sync();
            cur ^= 1;
        }
        obs_phase(t, Y, mask, g_h[cur], out, off_traj, off_lasth, tlast);
        grid_sync();
    }
    // h_fin copy
    const int gtid = blockIdx.x * NTHR + threadIdx.x;
    const float* h = g_h[cur];
    for (int idx = gtid; idx < BB * (2 * D0V + IDD); idx += G_CTAS * NTHR) {
        const int b = idx / 1040;
        const int c = idx - b * 1040;
        out[off_hfin + idx] = h[b * HS + c];
    }
}

// ---------------- init kernels ----------------
__global__ void init_kernel(const float* __restrict__ times, float* __restrict__ out,
                            long off_times, long off_lasth) {
    const int gtid = blockIdx.x * blockDim.x + threadIdx.x;
    const int nth = gridDim.x * blockDim.x;
    float* hall = &g_h[0][0];
    for (int i = gtid; i < 2 * BB * HS; i += nth) hall[i] = 0.f;
    for (int i = gtid; i < BB * D0V; i += nth) out[off_lasth + i] = 0.f;
    if (gtid < TT) out[off_times + gtid] = times[gtid];
    if (gtid == 0) { g_bar_cnt = 0u; g_bar_gen = 0u; }
}

__global__ void tlast_kernel(const float* __restrict__ mask) {
    __shared__ int anyt[TT];
    const int tid = threadIdx.x;
    if (tid < TT) {
        int a = 0;
        for (int b = 0; b < BB; b++)
            if (mask[b * TT + tid] > 0.f) { a = 1; break; }
        anyt[tid] = a;
    }
    __syncthreads();
    if (tid == 0) {
        int tl = -1;
        for (int t = TT - 1; t >= 0; t--)
            if (anyt[t]) { tl = t; break; }
        g_tlast = tl;
    }
}

// ---------------- launch ----------------
extern "C" void kernel_launch(void* const* d_in, const int* in_sizes, int n_in,
                              void* d_out, int out_size) {
    const float* times = (const float*)d_in[0];
    const float* Y     = (const float*)d_in[1];
    const float* mask  = (const float*)d_in[2];
    const float* A     = (const float*)d_in[3];
    const float* Bv    = (const float*)d_in[4];
    const float* W1    = (const float*)d_in[5];
    const float* b1    = (const float*)d_in[6];
    const float* W2    = (const float*)d_in[7];
    const float* b2    = (const float*)d_in[8];
    const float* W3    = (const float*)d_in[9];
    const float* b3    = (const float*)d_in[10];
    float* out = (float*)d_out;

    const long np = (long)BB * TT * IDD;          // 204800
    long off_traj, off_times, off_lasth, off_hfin;
    const long full = 2 * np + TT + (long)BB * D0V + (long)BB * (2 * D0V + IDD);  // 806962
    if ((long)out_size >= full) {
        off_traj = np;
        off_times = 2 * np;
    } else {
        off_traj = -1;          // y_traj aliased with y_preds in output layout
        off_times = np;
    }
    off_lasth = off_times + TT;
    off_hfin = off_lasth + (long)BB * D0V;

    init_kernel<<<64, 256>>>(times, out, off_times, off_lasth);
    tlast_kernel<<<1, 64>>>(mask);
    cnode_persistent<<<G_CTAS, NTHR>>>(Y, mask, A, Bv, W1, b1, W2, b2, W3, b3,
                                       out, off_traj, off_lasth, off_hfin);
}

// round 4
// speedup vs baseline: 1.1617x; 1.1617x over previous
#include <cuda_runtime.h>

// ---------------- problem constants ----------------
#define BB      256
#define TT      50
#define IDD     16
#define NCV     32
#define D0V     512
#define DINV    528
#define HIDV    512
#define NSTEPS  5
#define DT_C    0.05f

#define HS      1056            // padded row stride of h (1040 used; pad stays zero)
#define G_CTAS  136             // 8 groups x 17 CTAs
#define NTHR    256

// ---------------- dynamic smem layout (floats) ----------------
// Wq layout: per 2-k pair kp, 16 float4 quads {w_k(2c), w_k(2c+1), w_k1(2c), w_k1(2c+1)}
// W1: 272 kp x 64 ; W2: 256 kp x 64 ; W3: 256 kp x 64
// Xd: double buffer, per 32-k chunk: 16 kp x (32 rows x float4 dup), kp stride 132
#define WS1_OFF 0
#define WS2_OFF (272 * 64)                    // 17408
#define WS3_OFF (WS2_OFF + 256 * 64)          // 33792
#define XD_OFF  (WS3_OFF + 256 * 64)          // 50176
#define XD_BUF  (16 * 132)                    // 2112 floats per chunk buffer
#define SMEM_FLOATS (XD_OFF + 2 * XD_BUF)     // 54400
#define SMEM_BYTES  (SMEM_FLOATS * 4)         // 217600 B (< 227KB opt-in)

// ---------------- device scratch ----------------
__device__ float g_h[2][BB * HS];
__device__ float g_a0[BB * HIDV];
__device__ float g_a1[BB * HIDV];
__device__ int   g_tlast;
__device__ unsigned g_cnt[8 * 32];            // per-group barrier counters (128B apart)
__device__ volatile unsigned g_gen[8 * 32];

// ---------------- per-group barrier (17 CTAs, co-resident) ----------------
__device__ __forceinline__ void group_sync(int rb) {
    __syncthreads();
    if (threadIdx.x == 0) {
        const int s = rb * 32;
        unsigned gen = g_gen[s];
        __threadfence();
        if (atomicAdd(&g_cnt[s], 1u) == 16u) {
            g_cnt[s] = 0u;
            __threadfence();
            g_gen[s] = gen + 1u;
        } else {
            while (g_gen[s] == gen) { }
        }
        __threadfence();
    }
    __syncthreads();
}

// ---------------- f32x2 helpers ----------------
__device__ __forceinline__ void ffma2_acc(unsigned long long& acc,
                                          unsigned long long a,
                                          unsigned long long b) {
    asm("fma.rn.f32x2 %0, %1, %2, %0;" : "+l"(acc) : "l"(a), "l"(b));
}
__device__ __forceinline__ void unpack2(unsigned long long v, float& lo, float& hi) {
    asm("mov.b64 {%0, %1}, %2;" : "=f"(lo), "=f"(hi) : "l"(v));
}

struct U2x2 { unsigned long long lo, hi; };
__device__ __forceinline__ U2x2 lds128_u2(const float* p) {
    U2x2 r;
    asm("ld.shared.v2.b64 {%0, %1}, [%2];"
        : "=l"(r.lo), "=l"(r.hi) : "l"((unsigned long long)__cvta_generic_to_shared(p)));
    return r;
}

// ---------------- GEMM phase: 32x32 tile, resident k-paired W ----------------
// MODE 0/1: outbuf[row*512 + col] = relu(X@W + bias)
// MODE 2  : hn[row*HS + 512+col] = hc[row*HS + 512+col] + DT*(X@W + bias), col<528
template <int MODE>
__device__ __forceinline__ void gemm_phase(const float* __restrict__ X, int xs, int nkc,
                                           const float* __restrict__ Wq,
                                           const float* __restrict__ bias,
                                           float* __restrict__ outbuf,
                                           const float* __restrict__ hc,
                                           float* __restrict__ hn,
                                           float* __restrict__ Xd,
                                           int r0, int c0) {
    const int tid = threadIdx.x;
    const int lrow = tid >> 3;            // 0..31
    const int lkq  = (tid & 7) * 4;       // 0,4,..,28
    const int kp0  = lkq >> 1;            // 0,2,..,14
    const int tr = tid >> 4;              // 0..15
    const int tc = tid & 15;              // 0..15

    const float* xrow = X + (r0 + lrow) * xs + lkq;

    unsigned long long acc0 = 0ull, acc1 = 0ull;   // {col 2tc, 2tc+1} for rows 2tr / 2tr+1

    float4 pre = *(const float4*)(xrow);
    {
        float* d = Xd;
        *(float4*)(d + kp0 * 132 + lrow * 4)       = make_float4(pre.x, pre.x, pre.y, pre.y);
        *(float4*)(d + (kp0 + 1) * 132 + lrow * 4) = make_float4(pre.z, pre.z, pre.w, pre.w);
    }
    if (nkc > 1) pre = *(const float4*)(xrow + 32);
    __syncthreads();

    for (int kc = 0; kc < nkc; kc++) {
        if (kc + 1 < nkc) {
            float* d = Xd + ((kc + 1) & 1) * XD_BUF;
            *(float4*)(d + kp0 * 132 + lrow * 4)       = make_float4(pre.x, pre.x, pre.y, pre.y);
            *(float4*)(d + (kp0 + 1) * 132 + lrow * 4) = make_float4(pre.z, pre.z, pre.w, pre.w);
        }
        if (kc + 2 < nkc) pre = *(const float4*)(xrow + (kc + 2) * 32);

        const float* xb = Xd + (kc & 1) * XD_BUF + 2 * tr * 4;
        const float* wb = Wq + kc * 16 * 64 + tc * 4;
        #pragma unroll
        for (int kp = 0; kp < 16; kp++) {
            U2x2 x0 = lds128_u2(xb + kp * 132);        // {x_k(r0) dup | x_k1(r0) dup}
            U2x2 x1 = lds128_u2(xb + kp * 132 + 4);    // row r0+1
            U2x2 w  = lds128_u2(wb + kp * 64);         // {w_k pair | w_k1 pair}
            ffma2_acc(acc0, x0.lo, w.lo);
            ffma2_acc(acc0, x0.hi, w.hi);
            ffma2_acc(acc1, x1.lo, w.lo);
            ffma2_acc(acc1, x1.hi, w.hi);
        }
        __syncthreads();
    }

    float a00, a01, a10, a11;
    unpack2(acc0, a00, a01);
    unpack2(acc1, a10, a11);

    const int ra = r0 + 2 * tr;
    const int ca = c0 + 2 * tc;
    if (MODE != 2) {
        float b0 = bias[ca], b1v = bias[ca + 1];
        *(float2*)&outbuf[ra * 512 + ca] =
            make_float2(fmaxf(a00 + b0, 0.f), fmaxf(a01 + b1v, 0.f));
        *(float2*)&outbuf[(ra + 1) * 512 + ca] =
            make_float2(fmaxf(a10 + b0, 0.f), fmaxf(a11 + b1v, 0.f));
    } else {
        if (ca < DINV) {
            float b0 = bias[ca];
            hn[ra * HS + 512 + ca] = hc[ra * HS + 512 + ca] + DT_C * (a00 + b0);
            hn[(ra + 1) * HS + 512 + ca] = hc[(ra + 1) * HS + 512 + ca] + DT_C * (a10 + b0);
        }
        if (ca + 1 < DINV) {
            float b1v = bias[ca + 1];
            hn[ra * HS + 512 + ca + 1] = hc[ra * HS + 512 + ca + 1] + DT_C * (a01 + b1v);
            hn[(ra + 1) * HS + 512 + ca + 1] = hc[(ra + 1) * HS + 512 + ca + 1] + DT_C * (a11 + b1v);
        }
    }
}

// ---------------- cn0 ODE phase (j==16 CTA of each group) ----------------
__device__ __forceinline__ void cnode_phase(int rb,
                                            const float* __restrict__ A,
                                            const float* __restrict__ Bv,
                                            const float* __restrict__ hc,
                                            float* __restrict__ hn,
                                            float* __restrict__ As,
                                            float* __restrict__ Bs) {
    const int tid = threadIdx.x;
    for (int i = tid; i < NCV * NCV; i += NTHR) As[i] = A[i];
    if (tid < NCV) Bs[tid] = Bv[tid];
    __syncthreads();

    const int b0 = rb * 32;
    #pragma unroll
    for (int rep = 0; rep < 2; rep++) {
        const int item = rep * 256 + tid;       // 0..511
        const int b = b0 + (item >> 4);
        const int i = item & 15;
        const float* hr = hc + b * HS;
        float x[32];
        const float4* cp = (const float4*)(hr + i * 32);
        #pragma unroll
        for (int q = 0; q < 8; q++) {
            float4 v = cp[q];
            x[4 * q] = v.x; x[4 * q + 1] = v.y; x[4 * q + 2] = v.z; x[4 * q + 3] = v.w;
        }
        const float cn1v = hr[512 + i];
        float* outp = hn + b * HS + i * 32;
        #pragma unroll 4
        for (int n = 0; n < 32; n++) {
            float acc = Bs[n] * cn1v;
            const float4* ap = (const float4*)(As + n * 32);
            #pragma unroll
            for (int q = 0; q < 8; q++) {
                float4 a4 = ap[q];
                acc = fmaf(x[4 * q], a4.x, acc);
                acc = fmaf(x[4 * q + 1], a4.y, acc);
                acc = fmaf(x[4 * q + 2], a4.z, acc);
                acc = fmaf(x[4 * q + 3], a4.w, acc);
            }
            outp[n] = x[n] + DT_C * acc;
        }
    }
    __syncthreads();
}

// ---------------- observation update (group-local) ----------------
__device__ __forceinline__ void obs_phase(int rb, int j, int t,
                                          const float* __restrict__ Y,
                                          const float* __restrict__ mask,
                                          float* __restrict__ h,
                                          float* __restrict__ out,
                                          long off_traj, long off_lasth, int tlast) {
    const int gid = j * NTHR + threadIdx.x;     // 0..4351
    const int nth = 17 * NTHR;
    const int b0 = rb * 32;
    for (int idx = gid; idx < 32 * DINV; idx += nth) {
        const int b = b0 + idx / DINV;
        const int c = idx % DINV;
        const float m = mask[b * TT + t];
        float* hr = h + b * HS;
        const float he = hr[512 + c];
        if (c < IDD) {
            const long po = (long)(b * TT + t) * IDD + c;
            out[po] = he;
            if (off_traj >= 0) out[off_traj + po] = he;
            const float y = Y[(b * TT + t) * IDD + c];
            hr[512 + c] = m * y + (1.f - m) * he;
        } else {
            const int jj = c - IDD;
            hr[512 + c] = m * hr[jj] + (1.f - m) * he;
        }
    }
    if (t == tlast) {
        for (int idx = gid; idx < 32 * D0V; idx += nth) {
            const int b = b0 + (idx >> 9);
            const int jj = idx & 511;
            out[off_lasth + (long)b * D0V + jj] = h[b * HS + jj];
        }
    }
}

// ---------------- persistent kernel ----------------
__global__ void __launch_bounds__(NTHR, 1)
cnode_persistent(const float* __restrict__ Y, const float* __restrict__ mask,
                 const float* __restrict__ A, const float* __restrict__ Bv,
                 const float* __restrict__ W1, const float* __restrict__ b1,
                 const float* __restrict__ W2, const float* __restrict__ b2,
                 const float* __restrict__ W3, const float* __restrict__ b3,
                 float* __restrict__ out,
                 long off_traj, long off_lasth, long off_hfin) {
    extern __shared__ float sm[];
    const int cta = blockIdx.x;
    const int tid = threadIdx.x;
    const int rb = cta / 17;          // row block 0..7 (batch rows rb*32..+31)
    const int j  = cta - rb * 17;     // 0..16
    const int r0 = rb * 32;
    const int c0 = j * 32;            // col tile origin (j==16 -> 512, GEMM3 only)

    // ---- load resident weights (k-paired quad layout) ----
    if (j < 16) {
        for (int idx = tid; idx < 272 * 64; idx += NTHR) {
            const int kp = idx >> 6, r = idx & 63;
            const int tcq = r >> 2, e = r & 3;
            const int k = 2 * kp + (e >> 1);
            const int c = c0 + 2 * tcq + (e & 1);
            sm[WS1_OFF + idx] = (k < DINV) ? W1[k * HIDV + c] : 0.f;
        }
        for (int idx = tid; idx < 256 * 64; idx += NTHR) {
            const int kp = idx >> 6, r = idx & 63;
            const int tcq = r >> 2, e = r & 3;
            const int k = 2 * kp + (e >> 1);
            const int c = c0 + 2 * tcq + (e & 1);
            sm[WS2_OFF + idx] = W2[k * HIDV + c];
        }
    }
    for (int idx = tid; idx < 256 * 64; idx += NTHR) {
        const int kp = idx >> 6, r = idx & 63;
        const int tcq = r >> 2, e = r & 3;
        const int k = 2 * kp + (e >> 1);
        const int c = c0 + 2 * tcq + (e & 1);
        sm[WS3_OFF + idx] = (c < DINV) ? W3[k * DINV + c] : 0.f;
    }
    __syncthreads();

    float* Xd = sm + XD_OFF;

    int cur = 0;
    const int tlast = g_tlast;
    for (int t = 0; t < TT; t++) {
        for (int s = 0; s < NSTEPS; s++) {
            float* hc = g_h[cur];
            float* hn = g_h[cur ^ 1];
            // phase 1: GEMM1 (K=544 padded, 17 chunks) on j<16 ; cn_ode on j==16
            if (j < 16)
                gemm_phase<0>(hc + 512, HS, 17, sm + WS1_OFF, b1, g_a0,
                              nullptr, nullptr, Xd, r0, c0);
            else
                cnode_phase(rb, A, Bv, hc, hn, Xd, Xd + 1024);
            group_sync(rb);
            // phase 2: GEMM2 (K=512)
            if (j < 16)
                gemm_phase<1>(g_a0, HIDV, 16, sm + WS2_OFF, b2, g_a1,
                              nullptr, nullptr, Xd, r0, c0);
            group_sync(rb);
            // phase 3: GEMM3 (K=512) + euler update of cn1 part (all 17)
            gemm_phase<2>(g_a1, HIDV, 16, sm + WS3_OFF, b3, nullptr,
                          hc, hn, Xd, r0, c0);
            group_sync(rb);
            cur ^= 1;
        }
        obs_phase(rb, j, t, Y, mask, g_h[cur], out, off_traj, off_lasth, tlast);
        group_sync(rb);
    }
    // h_fin copy (group-local rows)
    const int gid = j * NTHR + tid;
    const float* h = g_h[cur];
    for (int idx = gid; idx < 32 * 1040; idx += 17 * NTHR) {
        const int b = rb * 32 + idx / 1040;
        const int c = idx % 1040;
        out[off_hfin + (long)b * 1040 + c] = h[b * HS + c];
    }
}

// ---------------- init kernels ----------------
__global__ void init_kernel(const float* __restrict__ times, float* __restrict__ out,
                            long off_times, long off_lasth) {
    const int gtid = blockIdx.x * blockDim.x + threadIdx.x;
    const int nth = gridDim.x * blockDim.x;
    float* hall = &g_h[0][0];
    for (int i = gtid; i < 2 * BB * HS; i += nth) hall[i] = 0.f;
    for (int i = gtid; i < BB * D0V; i += nth) out[off_lasth + i] = 0.f;
    if (gtid < TT) out[off_times + gtid] = times[gtid];
    if (gtid < 8 * 32) { g_cnt[gtid] = 0u; g_gen[gtid] = 0u; }
}

__global__ void tlast_kernel(const float* __restrict__ mask) {
    __shared__ int anyt[TT];
    const int tid = threadIdx.x;
    if (tid < TT) {
        int a = 0;
        for (int b = 0; b < BB; b++)
            if (mask[b * TT + tid] > 0.f) { a = 1; break; }
        anyt[tid] = a;
    }
    __syncthreads();
    if (tid == 0) {
        int tl = -1;
        for (int t = TT - 1; t >= 0; t--)
            if (anyt[t]) { tl = t; break; }
        g_tlast = tl;
    }
}

// ---------------- launch ----------------
extern "C" void kernel_launch(void* const* d_in, const int* in_sizes, int n_in,
                              void* d_out, int out_size) {
    const float* times = (const float*)d_in[0];
    const float* Y     = (const float*)d_in[1];
    const float* mask  = (const float*)d_in[2];
    const float* A     = (const float*)d_in[3];
    const float* Bv    = (const float*)d_in[4];
    const float* W1    = (const float*)d_in[5];
    const float* b1    = (const float*)d_in[6];
    const float* W2    = (const float*)d_in[7];
    const float* b2    = (const float*)d_in[8];
    const float* W3    = (const float*)d_in[9];
    const float* b3    = (const float*)d_in[10];
    float* out = (float*)d_out;

    cudaFuncSetAttribute(cnode_persistent,
                         cudaFuncAttributeMaxDynamicSharedMemorySize, SMEM_BYTES);

    const long np = (long)BB * TT * IDD;          // 204800
    long off_traj, off_times, off_lasth, off_hfin;
    const long full = 2 * np + TT + (long)BB * D0V + (long)BB * (2 * D0V + IDD);
    if ((long)out_size >= full) {
        off_traj = np;
        off_times = 2 * np;
    } else {
        off_traj = -1;
        off_times = np;
    }
    off_lasth = off_times + TT;
    off_hfin = off_lasth + (long)BB * D0V;

    init_kernel<<<64, 256>>>(times, out, off_times, off_lasth);
    tlast_kernel<<<1, 64>>>(mask);
    cnode_persistent<<<G_CTAS, NTHR, SMEM_BYTES>>>(Y, mask, A, Bv, W1, b1, W2, b2, W3, b3,
                                                   out, off_traj, off_lasth, off_hfin);
}